// round 11
// baseline (speedup 1.0000x reference)
#include <cuda_runtime.h>
#include <cuda_bf16.h>
#include <cstdint>

// Problem dims (fixed by the dataset)
#define T_STEPS 128
#define BATCH   128
#define D_IN    1024
#define D_OUT   1024
#define M_TOT   (T_STEPS * BATCH)   // 16384
#define BD      (BATCH * D_OUT)     // 131072

// GEMM tiling: 128x64 CTA tile, 256 threads, 8x(2x2)/thread
#define BM 128
#define BN 64
#define BK 16
#define TM 8
#define TJ 2                    // packed n-pairs per thread (4 n values)
#define NTHREADS 256
#define NITER   (D_IN / BK)     // 64
#define FOLD_IT 32              // iteration where K=512 chunk boundary falls

// Scratch for X = A @ W + b  (64 MB) — __device__ global, no allocation.
__device__ float g_X[(size_t)M_TOT * D_OUT];

typedef unsigned long long ull;

// Packed f32x2: two independent IEEE-rn fp32 ops per instruction.
// Per-lane results are bit-identical to scalar FFMA / FADD.rn.
__device__ __forceinline__ ull fma2(ull a, ull b, ull c) {
    ull d;
    asm("fma.rn.f32x2 %0, %1, %2, %3;" : "=l"(d) : "l"(a), "l"(b), "l"(c));
    return d;
}
__device__ __forceinline__ ull add2(ull a, ull b) {
    ull d;
    asm("add.rn.f32x2 %0, %1, %2;" : "=l"(d) : "l"(a), "l"(b));
    return d;
}
__device__ __forceinline__ float2 unpack2(ull v) {
    float2 f;
    asm("mov.b64 {%0, %1}, %2;" : "=f"(f.x), "=f"(f.y) : "l"(v));
    return f;
}

// ---------------------------------------------------------------------------
// Kernel 1: X[16384,1024] = A[16384,1024] @ W[1024,1024] + b
// Bit-exact split-K=2 ordering (PROVEN: rel_err == 0.0):
//   c0 = serial ascending FFMA over k=0..511
//   c1 = serial ascending FFMA over k=512..1023
//   X  = ((c0 + c1) + bias), each add separately rounded.
// BN=64 tile: 2048 CTAs -> 6.92 waves at 2 CTAs/SM (tail waste 1.2% vs
// 13.5% at BN=128). tot2 back in registers (no fold-stream traffic).
// ---------------------------------------------------------------------------
__global__ __launch_bounds__(NTHREADS, 2)
void sgemm_bias_splitk2_f32x2_kernel(const float* __restrict__ A,
                                     const float* __restrict__ W,
                                     const float* __restrict__ bias)
{
    __shared__ float As2[2][BK][2 * BM];   // duplicated A: 2 * 16KB
    __shared__ float Ws [2][BK][BN];       // 2 * 4KB

    const int bx = blockIdx.x;             // N tile (0..15)
    const int by = blockIdx.y;             // M tile (0..127)
    const int tid = threadIdx.x;
    const int tx = tid & 15;               // n sub (0..15)
    const int ty = tid >> 4;               // m sub (0..15), m = ty*8 + i

    const float* Ablk = A + (size_t)by * BM * D_IN;

    // A tile: 128 rows x 16 cols = 512 float4; 2 per thread
    const int a_row  = tid >> 2;           // 0..63 (+64)
    const int a_col4 = tid & 3;
    // W tile: 16 rows x 64 cols = 256 float4; 1 per thread
    const int w_row  = tid >> 4;           // 0..15
    const int w_col4 = tid & 15;

    float4 areg[2], wreg;

    auto load_tile = [&](int k0) {
        #pragma unroll
        for (int i = 0; i < 2; i++) {
            int r = a_row + i * 64;
            areg[i] = *reinterpret_cast<const float4*>(
                Ablk + (size_t)r * D_IN + k0 + a_col4 * 4);
        }
        wreg = *reinterpret_cast<const float4*>(
            W + (size_t)(k0 + w_row) * D_OUT + (size_t)bx * BN + w_col4 * 4);
    };
    auto store_tile = [&](int s) {
        #pragma unroll
        for (int i = 0; i < 2; i++) {
            int r = a_row + i * 64;
            *reinterpret_cast<float2*>(&As2[s][a_col4 * 4 + 0][2 * r]) =
                make_float2(areg[i].x, areg[i].x);
            *reinterpret_cast<float2*>(&As2[s][a_col4 * 4 + 1][2 * r]) =
                make_float2(areg[i].y, areg[i].y);
            *reinterpret_cast<float2*>(&As2[s][a_col4 * 4 + 2][2 * r]) =
                make_float2(areg[i].z, areg[i].z);
            *reinterpret_cast<float2*>(&As2[s][a_col4 * 4 + 3][2 * r]) =
                make_float2(areg[i].w, areg[i].w);
        }
        *reinterpret_cast<float4*>(&Ws[s][w_row][w_col4 * 4]) = wreg;
    };

    // acc2[i][j]: m = by*BM + ty*8 + i;  n = bx*BN + 32*j + 2*tx + {lo,hi}
    ull acc2[TM][TJ];
    ull tot2[TM][TJ];
    #pragma unroll
    for (int i = 0; i < TM; i++)
        #pragma unroll
        for (int j = 0; j < TJ; j++)
            acc2[i][j] = 0ULL;

    load_tile(0);
    store_tile(0);
    __syncthreads();
    int cur = 0;

    for (int it = 0; it < NITER; ++it) {
        if (it + 1 < NITER) load_tile((it + 1) * BK);

        if (it == FOLD_IT) {
            // chunk boundary: save c0, restart accumulator for c1
            #pragma unroll
            for (int i = 0; i < TM; i++)
                #pragma unroll
                for (int j = 0; j < TJ; j++) {
                    tot2[i][j] = acc2[i][j];
                    acc2[i][j] = 0ULL;
                }
        }

        #pragma unroll
        for (int k = 0; k < BK; k++) {
            // dup-A: 4x LDS.128 broadcast (2 distinct addrs per warp)
            const ulonglong2* asrc = reinterpret_cast<const ulonglong2*>(
                &As2[cur][k][2 * (ty * TM)]);
            ull a2[TM];
            #pragma unroll
            for (int ii = 0; ii < 4; ii++) {
                ulonglong2 v = asrc[ii];
                a2[2 * ii + 0] = v.x;
                a2[2 * ii + 1] = v.y;
            }
            // W: 2x LDS.64, banks 2*tx -> conflict-free
            ull w2[TJ];
            #pragma unroll
            for (int j = 0; j < TJ; j++)
                w2[j] = *reinterpret_cast<const ull*>(
                    &Ws[cur][k][32 * j + 2 * tx]);
            #pragma unroll
            for (int i = 0; i < TM; i++)
                #pragma unroll
                for (int j = 0; j < TJ; j++)
                    acc2[i][j] = fma2(a2[i], w2[j], acc2[i][j]);
        }

        if (it + 1 < NITER) {
            store_tile(cur ^ 1);
            __syncthreads();
            cur ^= 1;
        }
    }

    // final combine: tot = c0 + c1 (one rn add per lane)
    #pragma unroll
    for (int i = 0; i < TM; i++)
        #pragma unroll
        for (int j = 0; j < TJ; j++)
            tot2[i][j] = add2(tot2[i][j], acc2[i][j]);

    // Epilogue: + bias (one rn add per lane), coalesced float2 stores
    #pragma unroll
    for (int i = 0; i < TM; i++) {
        size_t row = (size_t)by * BM + ty * TM + i;
        #pragma unroll
        for (int j = 0; j < TJ; j++) {
            int col = bx * BN + 32 * j + 2 * tx;
            float2 p  = unpack2(tot2[i][j]);
            float2 bv = *reinterpret_cast<const float2*>(bias + col);
            float2 o;
            o.x = __fadd_rn(p.x, bv.x);
            o.y = __fadd_rn(p.y, bv.y);
            *reinterpret_cast<float2*>(g_X + row * D_OUT + col) = o;
        }
    }
}

// ---------------------------------------------------------------------------
// Kernel 2: LIF scan, 4 lanes per thread via float4, 128-thread blocks ->
// 256 blocks (covers all SMs; R7's mistake was 128 blocks). Per-lane
// arithmetic bit-identical to the proven scalar version.
// ---------------------------------------------------------------------------
__global__ __launch_bounds__(128)
void lif_scan_v4_kernel(float* __restrict__ out)
{
    int idx = blockIdx.x * blockDim.x + threadIdx.x;   // 0 .. BD/4-1
    const float4* src = reinterpret_cast<const float4*>(g_X) + idx;
    float4* dst = reinterpret_cast<float4*>(out) + idx;
    const int stride4 = BD / 4;

    float4 u = make_float4(0.f, 0.f, 0.f, 0.f);
    #pragma unroll 4
    for (int t = 0; t < T_STEPS; t++) {
        float4 x = src[(size_t)t * stride4];
        float4 s;
        u.x = __fadd_rn(__fmul_rn(0.75f, u.x), x.x);
        u.y = __fadd_rn(__fmul_rn(0.75f, u.y), x.y);
        u.z = __fadd_rn(__fmul_rn(0.75f, u.z), x.z);
        u.w = __fadd_rn(__fmul_rn(0.75f, u.w), x.w);
        s.x = (__fsub_rn(u.x, 1.0f) >= 0.0f) ? 1.0f : 0.0f;
        s.y = (__fsub_rn(u.y, 1.0f) >= 0.0f) ? 1.0f : 0.0f;
        s.z = (__fsub_rn(u.z, 1.0f) >= 0.0f) ? 1.0f : 0.0f;
        s.w = (__fsub_rn(u.w, 1.0f) >= 0.0f) ? 1.0f : 0.0f;
        dst[(size_t)t * stride4] = s;
        u.x = __fsub_rn(u.x, s.x);
        u.y = __fsub_rn(u.y, s.y);
        u.z = __fsub_rn(u.z, s.z);
        u.w = __fsub_rn(u.w, s.w);
    }
}

// ---------------------------------------------------------------------------
extern "C" void kernel_launch(void* const* d_in, const int* in_sizes, int n_in,
                              void* d_out, int out_size)
{
    const float* inputs = (const float*)d_in[0];   // [T, B, D_in]
    const float* W      = (const float*)d_in[1];   // [D_in, D_out]
    const float* bias   = (const float*)d_in[2];   // [D_out]
    float* out          = (float*)d_out;           // [T, B, D_out]

    dim3 gemm_grid(D_OUT / BN, M_TOT / BM);        // (16, 128) = 2048 CTAs
    sgemm_bias_splitk2_f32x2_kernel<<<gemm_grid, NTHREADS>>>(inputs, W, bias);

    lif_scan_v4_kernel<<<(BD / 4) / 128, 128>>>(out);
}

// round 12
// speedup vs baseline: 1.1785x; 1.1785x over previous
#include <cuda_runtime.h>
#include <cuda_bf16.h>
#include <cstdint>

// Problem dims (fixed by the dataset)
#define T_STEPS 128
#define BATCH   128
#define D_IN    1024
#define D_OUT   1024
#define M_TOT   (T_STEPS * BATCH)   // 16384
#define BD      (BATCH * D_OUT)     // 131072

// GEMM tiling: 64x128 CTA tile, 128 threads, TM=8 x TJ=4 (per-thread shape
// identical to the proven R10 kernel; only the CTA granularity halves).
#define BM 64
#define BN 128
#define BK 16
#define TM 8
#define TJ 4
#define NTHREADS 128
#define NITER   (D_IN / BK)     // 64
#define FOLD_IT 32              // iteration where K=512 chunk boundary falls

// Scratch for X = A @ W + b  (64 MB) — __device__ global, no allocation.
__device__ float g_X[(size_t)M_TOT * D_OUT];

typedef unsigned long long ull;

// Packed f32x2: two independent IEEE-rn fp32 ops per instruction.
// Per-lane results are bit-identical to scalar FFMA / FADD.rn.
__device__ __forceinline__ ull fma2(ull a, ull b, ull c) {
    ull d;
    asm("fma.rn.f32x2 %0, %1, %2, %3;" : "=l"(d) : "l"(a), "l"(b), "l"(c));
    return d;
}
__device__ __forceinline__ float2 unpack2(ull v) {
    float2 f;
    asm("mov.b64 {%0, %1}, %2;" : "=f"(f.x), "=f"(f.y) : "l"(v));
    return f;
}

// ---------------------------------------------------------------------------
// Kernel 1: X[16384,1024] = A[16384,1024] @ W[1024,1024] + b
// Bit-exact split-K=2 ordering (PROVEN: rel_err == 0.0):
//   c0 = serial ascending FFMA over k=0..511   (streamed to g_X at fold)
//   c1 = serial ascending FFMA over k=512..1023
//   X  = ((c0 + c1) + bias), each add separately rounded.
// 64x128 tile, 128 threads, 4 CTAs/SM: same 16 warps/SM and same per-warp
// smem pattern as the 791us R10 kernel, but half the drain-tail granularity
// (2048 CTAs, T_CTA ~114us).
// ---------------------------------------------------------------------------
__global__ __launch_bounds__(NTHREADS, 4)
void sgemm_bias_splitk2_f32x2_kernel(const float* __restrict__ A,
                                     const float* __restrict__ W,
                                     const float* __restrict__ bias)
{
    __shared__ float As2[2][BK][2 * BM];   // duplicated A: 2 * 8KB
    __shared__ float Ws [2][BK][BN];       // 2 * 8KB

    const int bx = blockIdx.x;             // N tile (0..7)
    const int by = blockIdx.y;             // M tile (0..255)
    const int tid = threadIdx.x;
    const int tx = tid & 15;               // n sub (0..15)
    const int ty = tid >> 4;               // m sub (0..7), m = ty*8 + i

    const float* Ablk = A + (size_t)by * BM * D_IN;

    // A tile: 64 rows x 16 cols = 256 float4; 2 per thread
    const int a_row  = tid >> 2;           // 0..31 (+32)
    const int a_col4 = tid & 3;
    // W tile: 16 rows x 128 cols = 512 float4; 4 per thread
    const int w_row  = tid >> 5;           // 0..3 (+4,+8,+12)
    const int w_col4 = tid & 31;

    float4 areg[2], wreg[4];

    auto load_tile = [&](int k0) {
        #pragma unroll
        for (int i = 0; i < 2; i++) {
            int r = a_row + i * 32;
            areg[i] = *reinterpret_cast<const float4*>(
                Ablk + (size_t)r * D_IN + k0 + a_col4 * 4);
        }
        #pragma unroll
        for (int i = 0; i < 4; i++) {
            int r = w_row + i * 4;
            wreg[i] = *reinterpret_cast<const float4*>(
                W + (size_t)(k0 + r) * D_OUT + (size_t)bx * BN + w_col4 * 4);
        }
    };
    auto store_tile = [&](int s) {
        #pragma unroll
        for (int i = 0; i < 2; i++) {
            int r = a_row + i * 32;
            *reinterpret_cast<float2*>(&As2[s][a_col4 * 4 + 0][2 * r]) =
                make_float2(areg[i].x, areg[i].x);
            *reinterpret_cast<float2*>(&As2[s][a_col4 * 4 + 1][2 * r]) =
                make_float2(areg[i].y, areg[i].y);
            *reinterpret_cast<float2*>(&As2[s][a_col4 * 4 + 2][2 * r]) =
                make_float2(areg[i].z, areg[i].z);
            *reinterpret_cast<float2*>(&As2[s][a_col4 * 4 + 3][2 * r]) =
                make_float2(areg[i].w, areg[i].w);
        }
        #pragma unroll
        for (int i = 0; i < 4; i++) {
            int r = w_row + i * 4;
            *reinterpret_cast<float4*>(&Ws[s][r][w_col4 * 4]) = wreg[i];
        }
    };

    // acc2[i][j]: m = by*BM + ty*8 + i;  n = bx*BN + 32*j + 2*tx + {lo,hi}
    ull acc2[TM][TJ];
    #pragma unroll
    for (int i = 0; i < TM; i++)
        #pragma unroll
        for (int j = 0; j < TJ; j++)
            acc2[i][j] = 0ULL;

    load_tile(0);
    store_tile(0);
    __syncthreads();
    int cur = 0;

    for (int it = 0; it < NITER; ++it) {
        if (it + 1 < NITER) load_tile((it + 1) * BK);

        if (it == FOLD_IT) {
            // chunk boundary: stream c0 to g_X (same cells the epilogue will
            // overwrite), then restart the accumulator for c1.
            #pragma unroll
            for (int i = 0; i < TM; i++) {
                size_t row = (size_t)by * BM + ty * TM + i;
                #pragma unroll
                for (int j = 0; j < TJ; j++) {
                    int col = bx * BN + 32 * j + 2 * tx;
                    *reinterpret_cast<float2*>(g_X + row * D_OUT + col) =
                        unpack2(acc2[i][j]);
                    acc2[i][j] = 0ULL;
                }
            }
        }

        #pragma unroll
        for (int k = 0; k < BK; k++) {
            // dup-A: 4x LDS.128 broadcast (2 distinct addrs per warp)
            const ulonglong2* asrc = reinterpret_cast<const ulonglong2*>(
                &As2[cur][k][2 * (ty * TM)]);
            ull a2[TM];
            #pragma unroll
            for (int ii = 0; ii < 4; ii++) {
                ulonglong2 v = asrc[ii];
                a2[2 * ii + 0] = v.x;
                a2[2 * ii + 1] = v.y;
            }
            // W: 4x LDS.64, banks 2*tx -> conflict-free broadcast
            ull w2[TJ];
            #pragma unroll
            for (int j = 0; j < TJ; j++)
                w2[j] = *reinterpret_cast<const ull*>(
                    &Ws[cur][k][32 * j + 2 * tx]);
            #pragma unroll
            for (int i = 0; i < TM; i++)
                #pragma unroll
                for (int j = 0; j < TJ; j++)
                    acc2[i][j] = fma2(a2[i], w2[j], acc2[i][j]);
        }

        if (it + 1 < NITER) {
            store_tile(cur ^ 1);
            __syncthreads();
            cur ^= 1;
        }
    }

    // Epilogue: reload c0, tot = (c0 + c1), out = tot + bias (each add
    // separately rounded, identical ordering to the proven version).
    #pragma unroll
    for (int i = 0; i < TM; i++) {
        size_t row = (size_t)by * BM + ty * TM + i;
        #pragma unroll
        for (int j = 0; j < TJ; j++) {
            int col = bx * BN + 32 * j + 2 * tx;
            float* dst = g_X + row * D_OUT + col;
            float2 c0 = *reinterpret_cast<const float2*>(dst);
            float2 c1 = unpack2(acc2[i][j]);
            float2 bv = *reinterpret_cast<const float2*>(bias + col);
            float2 o;
            o.x = __fadd_rn(__fadd_rn(c0.x, c1.x), bv.x);
            o.y = __fadd_rn(__fadd_rn(c0.y, c1.y), bv.y);
            *reinterpret_cast<float2*>(dst) = o;
        }
    }
}

// ---------------------------------------------------------------------------
// Kernel 2: LIF scan, 2 lanes per thread via float2, 256x256 (proven 22us).
// ---------------------------------------------------------------------------
__global__ __launch_bounds__(256)
void lif_scan_v2_kernel(float* __restrict__ out)
{
    int idx = blockIdx.x * blockDim.x + threadIdx.x;   // 0 .. BD/2-1
    const float2* src = reinterpret_cast<const float2*>(g_X) + idx;
    float2* dst = reinterpret_cast<float2*>(out) + idx;
    const int stride2 = BD / 2;

    float2 u = make_float2(0.f, 0.f);
    #pragma unroll 8
    for (int t = 0; t < T_STEPS; t++) {
        float2 x = src[(size_t)t * stride2];
        float2 s;
        u.x = __fadd_rn(__fmul_rn(0.75f, u.x), x.x);
        u.y = __fadd_rn(__fmul_rn(0.75f, u.y), x.y);
        s.x = (__fsub_rn(u.x, 1.0f) >= 0.0f) ? 1.0f : 0.0f;
        s.y = (__fsub_rn(u.y, 1.0f) >= 0.0f) ? 1.0f : 0.0f;
        dst[(size_t)t * stride2] = s;
        u.x = __fsub_rn(u.x, s.x);
        u.y = __fsub_rn(u.y, s.y);
    }
}

// ---------------------------------------------------------------------------
extern "C" void kernel_launch(void* const* d_in, const int* in_sizes, int n_in,
                              void* d_out, int out_size)
{
    const float* inputs = (const float*)d_in[0];   // [T, B, D_in]
    const float* W      = (const float*)d_in[1];   // [D_in, D_out]
    const float* bias   = (const float*)d_in[2];   // [D_out]
    float* out          = (float*)d_out;           // [T, B, D_out]

    dim3 gemm_grid(D_OUT / BN, M_TOT / BM);        // (8, 256) = 2048 CTAs
    sgemm_bias_splitk2_f32x2_kernel<<<gemm_grid, NTHREADS>>>(inputs, W, bias);

    lif_scan_v2_kernel<<<(BD / 2) / 256, 256>>>(out);
}

// round 13
// speedup vs baseline: 1.2981x; 1.1015x over previous
#include <cuda_runtime.h>
#include <cuda_bf16.h>
#include <cstdint>

// Problem dims (fixed by the dataset)
#define T_STEPS 128
#define BATCH   128
#define D_IN    1024
#define D_OUT   1024
#define M_TOT   (T_STEPS * BATCH)   // 16384
#define BD      (BATCH * D_OUT)     // 131072

// GEMM tiling (FROZEN proven shape): 128x128 CTA tile, 256 threads,
// TM=8 x TJ=4 per thread. Each CTA now computes ONE K-half (512) of a tile.
#define BM 128
#define BN 128
#define BK 16
#define TM 8
#define TJ 4
#define NTHREADS 256
#define NTILES   ((M_TOT / BM) * (D_OUT / BN))   // 1024
#define NITER_H  (512 / BK)                      // 32 k-iters per half

// Scratch for X = A @ W + b (64 MB) + per-tile c0-ready flags.
__device__ float    g_X[(size_t)M_TOT * D_OUT];
__device__ unsigned g_flag[NTILES];              // zero-init; restored to 0 each launch

typedef unsigned long long ull;

// Packed f32x2: two independent IEEE-rn fp32 ops per instruction.
// Per-lane results are bit-identical to scalar FFMA / FADD.rn.
__device__ __forceinline__ ull fma2(ull a, ull b, ull c) {
    ull d;
    asm("fma.rn.f32x2 %0, %1, %2, %3;" : "=l"(d) : "l"(a), "l"(b), "l"(c));
    return d;
}
__device__ __forceinline__ float2 unpack2(ull v) {
    float2 f;
    asm("mov.b64 {%0, %1}, %2;" : "=f"(f.x), "=f"(f.y) : "l"(v));
    return f;
}

// ---------------------------------------------------------------------------
// Kernel 1: X = A @ W + b with the bit-exact split-K=2 ordering (PROVEN):
//   c0 = serial ascending FFMA over k=0..511
//   c1 = serial ascending FFMA over k=512..1023
//   X  = ((c0 + c1) + bias), each add separately rounded.
// Grid = 2048 half-tile CTAs: bid<1024 -> c0 of tile bid (store + release
// flag); bid>=1024 -> c1 of tile bid-1024 (acquire flag, combine, reset).
// Half-size work quantum: 2048/296 slots = 6.92 waves -> 1.2% tail
// (vs 13.5% with 1024 full tiles).
// ---------------------------------------------------------------------------
__global__ __launch_bounds__(NTHREADS, 2)
void sgemm_bias_splitk2_half_kernel(const float* __restrict__ A,
                                    const float* __restrict__ W,
                                    const float* __restrict__ bias)
{
    __shared__ float As2[2][BK][2 * BM];   // duplicated A: 2 * 16KB
    __shared__ float Ws [2][BK][BN];       // 2 * 8KB

    const int bid   = blockIdx.x;
    const bool is_c1 = (bid >= NTILES);
    const int tile  = is_c1 ? (bid - NTILES) : bid;
    const int bx    = tile & 7;            // N tile (0..7)
    const int by    = tile >> 3;           // M tile (0..127)
    const int kbase = is_c1 ? 512 : 0;

    const int tid = threadIdx.x;
    const int tx = tid & 15;               // n sub (0..15)
    const int ty = tid >> 4;               // m sub (0..15), m = ty*8 + i

    const float* Ablk = A + (size_t)by * BM * D_IN;

    // A tile: 128 rows x 16 cols = 512 float4; 2 per thread
    const int a_row  = tid >> 2;           // 0..63 (+64)
    const int a_col4 = tid & 3;
    // W tile: 16 rows x 128 cols = 512 float4; 2 per thread
    const int w_row  = tid >> 5;           // 0..7 (+8)
    const int w_col4 = tid & 31;

    float4 areg[2], wreg[2];

    auto load_tile = [&](int k0) {
        #pragma unroll
        for (int i = 0; i < 2; i++) {
            int r = a_row + i * 64;
            areg[i] = *reinterpret_cast<const float4*>(
                Ablk + (size_t)r * D_IN + k0 + a_col4 * 4);
        }
        #pragma unroll
        for (int i = 0; i < 2; i++) {
            int r = w_row + i * 8;
            wreg[i] = *reinterpret_cast<const float4*>(
                W + (size_t)(k0 + r) * D_OUT + (size_t)bx * BN + w_col4 * 4);
        }
    };
    auto store_tile = [&](int s) {
        #pragma unroll
        for (int i = 0; i < 2; i++) {
            int r = a_row + i * 64;
            *reinterpret_cast<float2*>(&As2[s][a_col4 * 4 + 0][2 * r]) =
                make_float2(areg[i].x, areg[i].x);
            *reinterpret_cast<float2*>(&As2[s][a_col4 * 4 + 1][2 * r]) =
                make_float2(areg[i].y, areg[i].y);
            *reinterpret_cast<float2*>(&As2[s][a_col4 * 4 + 2][2 * r]) =
                make_float2(areg[i].z, areg[i].z);
            *reinterpret_cast<float2*>(&As2[s][a_col4 * 4 + 3][2 * r]) =
                make_float2(areg[i].w, areg[i].w);
        }
        #pragma unroll
        for (int i = 0; i < 2; i++) {
            int r = w_row + i * 8;
            *reinterpret_cast<float4*>(&Ws[s][r][w_col4 * 4]) = wreg[i];
        }
    };

    // acc2[i][j]: m = by*BM + ty*8 + i;  n = bx*BN + 32*j + 2*tx + {lo,hi}
    ull acc2[TM][TJ];
    #pragma unroll
    for (int i = 0; i < TM; i++)
        #pragma unroll
        for (int j = 0; j < TJ; j++)
            acc2[i][j] = 0ULL;

    load_tile(kbase);
    store_tile(0);
    __syncthreads();
    int cur = 0;

    for (int it = 0; it < NITER_H; ++it) {
        if (it + 1 < NITER_H) load_tile(kbase + (it + 1) * BK);

        #pragma unroll
        for (int k = 0; k < BK; k++) {
            // dup-A: 4x LDS.128 broadcast (2 distinct addrs per warp)
            const ulonglong2* asrc = reinterpret_cast<const ulonglong2*>(
                &As2[cur][k][2 * (ty * TM)]);
            ull a2[TM];
            #pragma unroll
            for (int ii = 0; ii < 4; ii++) {
                ulonglong2 v = asrc[ii];
                a2[2 * ii + 0] = v.x;
                a2[2 * ii + 1] = v.y;
            }
            // W: 4x LDS.64, banks 2*tx -> conflict-free
            ull w2[TJ];
            #pragma unroll
            for (int j = 0; j < TJ; j++)
                w2[j] = *reinterpret_cast<const ull*>(
                    &Ws[cur][k][32 * j + 2 * tx]);
            #pragma unroll
            for (int i = 0; i < TM; i++)
                #pragma unroll
                for (int j = 0; j < TJ; j++)
                    acc2[i][j] = fma2(a2[i], w2[j], acc2[i][j]);
        }

        if (it + 1 < NITER_H) {
            store_tile(cur ^ 1);
            __syncthreads();
            cur ^= 1;
        }
    }

    if (!is_c1) {
        // c0 producer: store raw c0, then publish with a release flag.
        #pragma unroll
        for (int i = 0; i < TM; i++) {
            size_t row = (size_t)by * BM + ty * TM + i;
            #pragma unroll
            for (int j = 0; j < TJ; j++) {
                int col = bx * BN + 32 * j + 2 * tx;
                *reinterpret_cast<float2*>(g_X + row * D_OUT + col) =
                    unpack2(acc2[i][j]);
            }
        }
        __syncthreads();
        if (tid == 0) {
            asm volatile("st.global.release.gpu.u32 [%0], %1;"
                         :: "l"(&g_flag[tile]), "r"(1u) : "memory");
        }
    } else {
        // c1 consumer: wait for c0 (acquire), combine with frozen rounding
        // ((c0 + c1) + bias), store final, reset flag for the next replay.
        if (tid == 0) {
            unsigned v = 0;
            do {
                asm volatile("ld.global.acquire.gpu.u32 %0, [%1];"
                             : "=r"(v) : "l"(&g_flag[tile]) : "memory");
                if (v == 0) __nanosleep(64);
            } while (v == 0);
        }
        __syncthreads();

        #pragma unroll
        for (int i = 0; i < TM; i++) {
            size_t row = (size_t)by * BM + ty * TM + i;
            #pragma unroll
            for (int j = 0; j < TJ; j++) {
                int col = bx * BN + 32 * j + 2 * tx;
                float* dst = g_X + row * D_OUT + col;
                float2 c0;
                asm volatile("ld.global.cg.v2.f32 {%0, %1}, [%2];"
                             : "=f"(c0.x), "=f"(c0.y) : "l"(dst) : "memory");
                float2 c1 = unpack2(acc2[i][j]);
                float2 bv = *reinterpret_cast<const float2*>(bias + col);
                float2 o;
                o.x = __fadd_rn(__fadd_rn(c0.x, c1.x), bv.x);
                o.y = __fadd_rn(__fadd_rn(c0.y, c1.y), bv.y);
                *reinterpret_cast<float2*>(dst) = o;
            }
        }
        __syncthreads();
        if (tid == 0) g_flag[tile] = 0;    // restore launch-invariant state
    }
}

// ---------------------------------------------------------------------------
// Kernel 2: LIF scan, 2 lanes per thread via float2, 256x256 (proven 22us).
// ---------------------------------------------------------------------------
__global__ __launch_bounds__(256)
void lif_scan_v2_kernel(float* __restrict__ out)
{
    int idx = blockIdx.x * blockDim.x + threadIdx.x;   // 0 .. BD/2-1
    const float2* src = reinterpret_cast<const float2*>(g_X) + idx;
    float2* dst = reinterpret_cast<float2*>(out) + idx;
    const int stride2 = BD / 2;

    float2 u = make_float2(0.f, 0.f);
    #pragma unroll 8
    for (int t = 0; t < T_STEPS; t++) {
        float2 x = src[(size_t)t * stride2];
        float2 s;
        u.x = __fadd_rn(__fmul_rn(0.75f, u.x), x.x);
        u.y = __fadd_rn(__fmul_rn(0.75f, u.y), x.y);
        s.x = (__fsub_rn(u.x, 1.0f) >= 0.0f) ? 1.0f : 0.0f;
        s.y = (__fsub_rn(u.y, 1.0f) >= 0.0f) ? 1.0f : 0.0f;
        dst[(size_t)t * stride2] = s;
        u.x = __fsub_rn(u.x, s.x);
        u.y = __fsub_rn(u.y, s.y);
    }
}

// ---------------------------------------------------------------------------
extern "C" void kernel_launch(void* const* d_in, const int* in_sizes, int n_in,
                              void* d_out, int out_size)
{
    const float* inputs = (const float*)d_in[0];   // [T, B, D_in]
    const float* W      = (const float*)d_in[1];   // [D_in, D_out]
    const float* bias   = (const float*)d_in[2];   // [D_out]
    float* out          = (float*)d_out;           // [T, B, D_out]

    sgemm_bias_splitk2_half_kernel<<<2 * NTILES, NTHREADS>>>(inputs, W, bias);

    lif_scan_v2_kernel<<<(BD / 2) / 256, 256>>>(out);
}